// round 1
// baseline (speedup 1.0000x reference)
#include <cuda_runtime.h>
#include <math.h>

#define BB 4
#define LL 2048
#define DM 1024
#define DI 2048
#define DTR 64
#define M_TOK (BB*LL)           // 8192

// ---------------- scratch (device globals; allocation is forbidden) ----------
__device__ float g_xn   [M_TOK * DM];        // 33.5 MB  normed input
__device__ float g_xz   [M_TOK * (2*DI)];    // 134 MB   in-proj output (xc | z)
__device__ float g_xc   [M_TOK * DI];        // 67 MB    conv+squareplus output (scan u)
__device__ float g_dbl  [M_TOK * DTR];       // 2 MB     dt_rank projection
__device__ float g_decay[M_TOK * DI];        // 67 MB    quantized decay
__device__ float g_h    [M_TOK * DI];        // 67 MB    h, then y=h*sp(z) in-place
__device__ float g_Wq_in [4096*1024];
__device__ float g_Wq_x  [64*2048];          // only first 64 rows ever used
__device__ float g_Wq_dt [2048*64];
__device__ float g_Wq_out[1024*2048];
__device__ float g_scale[4];
__device__ float g_part [4*256];

// ---------------- exact reference math ---------------------------------------
__device__ __forceinline__ float squareplus_f(float x){
    float y = fminf(fmaxf(x*x + 4.0f, 1e-6f), 1e6f);
    // _rsqrt_newton ladder (order matters: later wheres override)
    float r = (y > 16.0f) ? 0.125f : 0.5f;
    if (y > 64.0f)  r = 0.0625f;
    if (y > 256.0f) r = 0.03125f;
    if (y < 4.0f)   r = 1.0f;
    if (y < 1.0f)   r = 2.0f;
    if (y < 0.25f)  r = 4.0f;
#pragma unroll
    for (int i = 0; i < 3; i++){
        r = r * (1.5f - 0.5f * y * r * r);
        r = fminf(fmaxf(r, 1e-6f), 1e3f);
    }
    float s = fminf(fmaxf(y * r, 0.0f), 1e3f);
    return 0.5f * (x + s);
}

__device__ __forceinline__ float decay_f(float z){
    float sg = 0.5f + 0.5f * z / (1.0f + fabsf(z));
    return rintf(sg * 32768.0f) * (1.0f / 32768.0f);   // round-half-even == jnp.round
}

// ---------------- weight scale: deterministic 2-level reduction --------------
__global__ void k_abs_partial(const float* __restrict__ W, int n, float* __restrict__ partial){
    __shared__ float sm[256];
    float s = 0.0f;
    for (int i = blockIdx.x * 256 + threadIdx.x; i < n; i += gridDim.x * 256)
        s += fabsf(W[i]);
    sm[threadIdx.x] = s; __syncthreads();
    for (int o = 128; o > 0; o >>= 1){
        if (threadIdx.x < o) sm[threadIdx.x] += sm[threadIdx.x + o];
        __syncthreads();
    }
    if (threadIdx.x == 0) partial[blockIdx.x] = sm[0];
}

__global__ void k_abs_final(const float* __restrict__ partial, float inv_n, float* __restrict__ out){
    __shared__ float sm[256];
    sm[threadIdx.x] = partial[threadIdx.x]; __syncthreads();
    for (int o = 128; o > 0; o >>= 1){
        if (threadIdx.x < o) sm[threadIdx.x] += sm[threadIdx.x + o];
        __syncthreads();
    }
    if (threadIdx.x == 0) *out = sm[0] * inv_n + 1e-8f;
}

__global__ void k_quant(const float* __restrict__ W, float* __restrict__ Wq, int n,
                        const float* __restrict__ sp){
    float s = *sp;
    for (int i = blockIdx.x * 256 + threadIdx.x; i < n; i += gridDim.x * 256){
        float t = rintf(W[i] / s);
        t = fminf(fmaxf(t, -1.0f), 1.0f);
        Wq[i] = t * s;
    }
}

// ---------------- bitshift norm (power-of-2 STE scale) ------------------------
__global__ void k_norm(const float* __restrict__ x, const float* __restrict__ gamma,
                       const float* __restrict__ step, float* __restrict__ xn){
    __shared__ float sm[256];
    __shared__ float s_mean, s_g;
    int row = blockIdx.x;
    const float4* xr = (const float4*)(x + (size_t)row * DM);
    float4 v = xr[threadIdx.x];
    sm[threadIdx.x] = v.x + v.y + v.z + v.w; __syncthreads();
    for (int o = 128; o > 0; o >>= 1){
        if (threadIdx.x < o) sm[threadIdx.x] += sm[threadIdx.x + o];
        __syncthreads();
    }
    if (threadIdx.x == 0) s_mean = sm[0] * (1.0f / DM);
    __syncthreads();
    float mean = s_mean;
    float cx = v.x - mean, cy = v.y - mean, cz = v.z - mean, cw = v.w - mean;
    sm[threadIdx.x] = cx*cx + cy*cy + cz*cz + cw*cw; __syncthreads();
    for (int o = 128; o > 0; o >>= 1){
        if (threadIdx.x < o) sm[threadIdx.x] += sm[threadIdx.x + o];
        __syncthreads();
    }
    if (threadIdx.x == 0){
        float var = sm[0] * (1.0f / DM);
        float vv = var + 1e-9f;
        float sc = 1.0f;
        if (vv >= 4.0f)     sc = 0.5f;
        if (vv >= 16.0f)    sc = 0.25f;
        if (vv >= 64.0f)    sc = 0.125f;
        if (vv >= 256.0f)   sc = 0.0625f;
        if (vv >= 1024.0f)  sc = 0.03125f;
        if (vv >= 4096.0f)  sc = 0.015625f;
        if (vv >= 16384.0f) sc = 0.0078125f;
        if (vv >= 65536.0f) sc = 0.00390625f;
        if (vv < 1.0f)      sc = 1.0f;
        if (vv < 0.25f)     sc = 2.0f;
        if (vv < 0.0625f)   sc = 4.0f;
        s_g = sc * step[0];
    }
    __syncthreads();
    float g = s_g;
    float4 gm = ((const float4*)gamma)[threadIdx.x];
    float4 o4 = make_float4(cx*g*gm.x, cy*g*gm.y, cz*g*gm.z, cw*g*gm.w);
    ((float4*)(xn + (size_t)row * DM))[threadIdx.x] = o4;
}

// ---------------- tiled SGEMM: C[M,N] = A[M,K] @ Bw[N,K]^T (+epilogue) --------
// EPI: 0 none, 1 decay(bias), 2 +residual
template<int BM, int BN, int BK, int TM, int TN, int EPI>
__global__ void k_gemm(const float* __restrict__ A, const float* __restrict__ Bw,
                       float* __restrict__ C, int M, int N, int K,
                       const float* __restrict__ bias, const float* __restrict__ resid){
    constexpr int THREADS = (BM/TM) * (BN/TN);
    __shared__ float As[BK][BM + 4];
    __shared__ float Bs[BK][BN + 4];
    const int tid  = threadIdx.x;
    const int tCol = tid % (BN/TN);
    const int tRow = tid / (BN/TN);
    const int m0 = blockIdx.y * BM, n0 = blockIdx.x * BN;
    float acc[TM][TN] = {};

    for (int kb = 0; kb < K; kb += BK){
#pragma unroll
        for (int i = tid; i < BM*BK/4; i += THREADS){
            int r = i / (BK/4), c4 = (i % (BK/4)) * 4;
            float4 v = *(const float4*)&A[(size_t)(m0 + r) * K + kb + c4];
            As[c4+0][r] = v.x; As[c4+1][r] = v.y; As[c4+2][r] = v.z; As[c4+3][r] = v.w;
        }
#pragma unroll
        for (int i = tid; i < BN*BK/4; i += THREADS){
            int r = i / (BK/4), c4 = (i % (BK/4)) * 4;
            float4 v = *(const float4*)&Bw[(size_t)(n0 + r) * K + kb + c4];
            Bs[c4+0][r] = v.x; Bs[c4+1][r] = v.y; Bs[c4+2][r] = v.z; Bs[c4+3][r] = v.w;
        }
        __syncthreads();
#pragma unroll
        for (int k = 0; k < BK; k++){
            float ra[TM], rb[TN];
#pragma unroll
            for (int i = 0; i < TM; i++) ra[i] = As[k][tRow*TM + i];
#pragma unroll
            for (int j = 0; j < TN; j++) rb[j] = Bs[k][tCol*TN + j];
#pragma unroll
            for (int i = 0; i < TM; i++)
#pragma unroll
                for (int j = 0; j < TN; j++) acc[i][j] += ra[i] * rb[j];
        }
        __syncthreads();
    }

#pragma unroll
    for (int i = 0; i < TM; i++){
        int m = m0 + tRow*TM + i;
#pragma unroll
        for (int j = 0; j < TN; j++){
            int n = n0 + tCol*TN + j;
            float v = acc[i][j];
            if (EPI == 1)      v = decay_f(v + bias[n]);
            else if (EPI == 2) v = v + resid[(size_t)m * N + n];
            C[(size_t)m * N + n] = v;
        }
    }
}

// ---------------- causal depthwise conv1d(k=4) + squareplus ------------------
__global__ void k_conv(const float* __restrict__ xz, const float* __restrict__ cw,
                       const float* __restrict__ cb, float* __restrict__ out, int total){
    for (int idx = blockIdx.x * 256 + threadIdx.x; idx < total; idx += gridDim.x * 256){
        int d = idx & (DI - 1);
        int t = (idx >> 11) & (LL - 1);
        int b = idx >> 22;
        const float* base = xz + (size_t)(b * LL) * (2*DI) + d;   // xc half of xz
        float w0 = cw[d*4+0], w1 = cw[d*4+1], w2 = cw[d*4+2], w3 = cw[d*4+3];
        float s = cb[d];
        if (t >= 3){
            s += w0 * base[(size_t)(t-3) * (2*DI)];
            s += w1 * base[(size_t)(t-2) * (2*DI)];
            s += w2 * base[(size_t)(t-1) * (2*DI)];
            s += w3 * base[(size_t)(t  ) * (2*DI)];
        } else {
            if (t-3 >= -0x7fffffff){} // keep compiler calm
            if (t >= 0) s += w3 * base[(size_t)t * (2*DI)];
            if (t >= 1) s += w2 * base[(size_t)(t-1) * (2*DI)];
            if (t >= 2) s += w1 * base[(size_t)(t-2) * (2*DI)];
        }
        out[idx] = squareplus_f(s);
    }
}

// ---------------- chunked linear-recurrence scan + y=h*sp(z) fusion ----------
// block: 32 channels (x) x 8 time slices (y); grid: (DI/32, B)
__global__ void k_scan(const float* __restrict__ u, const float* __restrict__ a,
                       const float* __restrict__ xz, float* __restrict__ y){
    const int c = blockIdx.x * 32 + threadIdx.x;
    const int b = blockIdx.y;
    const int slice = threadIdx.y;
    const int CH = LL / 8;   // 256
    size_t base = ((size_t)b * LL) * DI + c;
    int t0 = slice * CH;

    float A = 1.0f, Bv = 0.0f;
    size_t idx = base + (size_t)t0 * DI;
    for (int t = 0; t < CH; t++, idx += DI){
        float at = a[idx], ut = u[idx];
        Bv = at * Bv + (1.0f - at) * ut;
        A *= at;
    }
    __shared__ float sA[8][32], sB[8][32], sP[8][32];
    sA[slice][threadIdx.x] = A;
    sB[slice][threadIdx.x] = Bv;
    __syncthreads();
    if (slice == 0){
        float carry = 0.0f;
#pragma unroll
        for (int s2 = 0; s2 < 8; s2++){
            sP[s2][threadIdx.x] = carry;
            carry = sA[s2][threadIdx.x] * carry + sB[s2][threadIdx.x];
        }
    }
    __syncthreads();
    float h = sP[slice][threadIdx.x];
    idx = base + (size_t)t0 * DI;
    size_t zidx = ((size_t)b * LL + t0) * (2*DI) + DI + c;
    for (int t = 0; t < CH; t++, idx += DI, zidx += 2*DI){
        float at = a[idx], ut = u[idx];
        h = at * h + (1.0f - at) * ut;
        y[idx] = h * squareplus_f(xz[zidx]);
    }
}

// ---------------- launch ------------------------------------------------------
extern "C" void kernel_launch(void* const* d_in, const int* in_sizes, int n_in,
                              void* d_out, int out_size){
    const float* x     = (const float*)d_in[0];
    const float* gamma = (const float*)d_in[1];
    const float* step  = (const float*)d_in[2];
    const float* W_in  = (const float*)d_in[3];
    const float* cw    = (const float*)d_in[4];
    const float* cb    = (const float*)d_in[5];
    const float* W_x   = (const float*)d_in[6];
    const float* W_dt  = (const float*)d_in[7];
    const float* b_dt  = (const float*)d_in[8];
    const float* W_out = (const float*)d_in[9];
    float* out = (float*)d_out;

    float *p_xn, *p_xz, *p_xc, *p_dbl, *p_decay, *p_h;
    float *p_Win, *p_Wx, *p_Wdt, *p_Wout, *p_scale, *p_part;
    cudaGetSymbolAddress((void**)&p_xn,    g_xn);
    cudaGetSymbolAddress((void**)&p_xz,    g_xz);
    cudaGetSymbolAddress((void**)&p_xc,    g_xc);
    cudaGetSymbolAddress((void**)&p_dbl,   g_dbl);
    cudaGetSymbolAddress((void**)&p_decay, g_decay);
    cudaGetSymbolAddress((void**)&p_h,     g_h);
    cudaGetSymbolAddress((void**)&p_Win,   g_Wq_in);
    cudaGetSymbolAddress((void**)&p_Wx,    g_Wq_x);
    cudaGetSymbolAddress((void**)&p_Wdt,   g_Wq_dt);
    cudaGetSymbolAddress((void**)&p_Wout,  g_Wq_out);
    cudaGetSymbolAddress((void**)&p_scale, g_scale);
    cudaGetSymbolAddress((void**)&p_part,  g_part);

    // 1) ternary weight scales (mean|W| over FULL matrices) + quantization
    k_abs_partial<<<256,256>>>(W_in,  4096*1024, p_part + 0*256);
    k_abs_final  <<<1,256>>>(p_part + 0*256, 1.0f/4194304.0f, p_scale + 0);
    k_abs_partial<<<256,256>>>(W_x,   96*2048,  p_part + 1*256);
    k_abs_final  <<<1,256>>>(p_part + 1*256, 1.0f/196608.0f,  p_scale + 1);
    k_abs_partial<<<256,256>>>(W_dt,  2048*64,  p_part + 2*256);
    k_abs_final  <<<1,256>>>(p_part + 2*256, 1.0f/131072.0f,  p_scale + 2);
    k_abs_partial<<<256,256>>>(W_out, 1024*2048,p_part + 3*256);
    k_abs_final  <<<1,256>>>(p_part + 3*256, 1.0f/2097152.0f, p_scale + 3);

    k_quant<<<2048,256>>>(W_in,  p_Win,  4194304, p_scale + 0);
    k_quant<<<256, 256>>>(W_x,   p_Wx,   131072,  p_scale + 1);  // only first 64 rows used
    k_quant<<<256, 256>>>(W_dt,  p_Wdt,  131072,  p_scale + 2);
    k_quant<<<1024,256>>>(W_out, p_Wout, 2097152, p_scale + 3);

    // 2) norm
    k_norm<<<M_TOK,256>>>(x, gamma, step, p_xn);

    // 3) in-projection: xz = xn @ Wq_in^T   [8192,4096]
    k_gemm<128,128,8,8,8,0><<<dim3(32,64),256>>>(p_xn, p_Win, p_xz, M_TOK, 4096, 1024, nullptr, nullptr);

    // 4) causal conv + squareplus -> xc
    k_conv<<<65536,256>>>(p_xz, cw, cb, p_xc, M_TOK * DI);

    // 5) dt_rank projection (only 64 of 96 cols needed): dbl = xc @ Wq_x[:64]^T
    k_gemm<128,64,8,8,4,0><<<dim3(1,64),256>>>(p_xc, p_Wx, p_dbl, M_TOK, 64, 2048, nullptr, nullptr);

    // 6) dt projection + fused sigmoid_algebraic + dyadic round -> decay
    k_gemm<128,128,8,8,8,1><<<dim3(16,64),256>>>(p_dbl, p_Wdt, p_decay, M_TOK, 2048, 64, b_dt, nullptr);

    // 7) scan + fused y = h * squareplus(z)
    k_scan<<<dim3(DI/32, BB), dim3(32,8)>>>(p_xc, p_decay, p_xz, p_h);

    // 8) out-projection + residual -> d_out
    k_gemm<128,128,8,8,8,2><<<dim3(8,64),256>>>(p_h, p_Wout, out, M_TOK, 1024, 2048, nullptr, x);
}

// round 3
// speedup vs baseline: 2.9490x; 2.9490x over previous
#include <cuda_runtime.h>
#include <cuda_bf16.h>
#include <math.h>
#include <stdint.h>

#define BB 4
#define LL 2048
#define DM 1024
#define DI 2048
#define DTR 64
#define M_TOK (BB*LL)           // 8192

typedef __nv_bfloat16 bf16;

// ---------------- scratch (device globals; allocation is forbidden) ----------
__device__ __align__(256) bf16  g_xn_h [M_TOK * DM];
__device__ __align__(256) bf16  g_xn_l [M_TOK * DM];
__device__ __align__(256) float g_xcraw[M_TOK * DI];      // conv input (pre-activation)
__device__ __align__(256) float g_spz  [M_TOK * DI];      // squareplus(z)
__device__ __align__(256) bf16  g_xc_h [M_TOK * DI];
__device__ __align__(256) bf16  g_xc_l [M_TOK * DI];
__device__ __align__(256) bf16  g_dbl_h[M_TOK * DTR];
__device__ __align__(256) bf16  g_dbl_l[M_TOK * DTR];
__device__ __align__(256) float g_decay[M_TOK * DI];
__device__ __align__(256) bf16  g_y_h  [M_TOK * DI];
__device__ __align__(256) bf16  g_y_l  [M_TOK * DI];
__device__ __align__(256) bf16  g_t_in [4096*1024];       // ternary {-1,0,1} exact in bf16
__device__ __align__(256) bf16  g_t_x  [64*2048];
__device__ __align__(256) bf16  g_t_dt [2048*64];
__device__ __align__(256) bf16  g_t_out[1024*2048];
__device__ __align__(256) float g_scale[4];
__device__ __align__(256) float g_part [4*256];

// ---------------- exact reference math ---------------------------------------
__device__ __forceinline__ float squareplus_f(float x){
    float y = fminf(fmaxf(x*x + 4.0f, 1e-6f), 1e6f);
    float r = (y > 16.0f) ? 0.125f : 0.5f;
    if (y > 64.0f)  r = 0.0625f;
    if (y > 256.0f) r = 0.03125f;
    if (y < 4.0f)   r = 1.0f;
    if (y < 1.0f)   r = 2.0f;
    if (y < 0.25f)  r = 4.0f;
#pragma unroll
    for (int i = 0; i < 3; i++){
        r = r * (1.5f - 0.5f * y * r * r);
        r = fminf(fmaxf(r, 1e-6f), 1e3f);
    }
    float s = fminf(fmaxf(y * r, 0.0f), 1e3f);
    return 0.5f * (x + s);
}

__device__ __forceinline__ float decay_f(float z){
    float sg = 0.5f + 0.5f * z / (1.0f + fabsf(z));
    return rintf(sg * 32768.0f) * (1.0f / 32768.0f);
}

__device__ __forceinline__ void split_bf(float v, bf16& h, bf16& l){
    h = __float2bfloat16_rn(v);
    l = __float2bfloat16_rn(v - __bfloat162float(h));
}

// ---------------- weight scale: deterministic 2-level reduction --------------
__global__ void k_abs_partial(const float* __restrict__ W, int n, float* __restrict__ partial){
    __shared__ float sm[256];
    float s = 0.0f;
    for (int i = blockIdx.x * 256 + threadIdx.x; i < n; i += gridDim.x * 256)
        s += fabsf(W[i]);
    sm[threadIdx.x] = s; __syncthreads();
    for (int o = 128; o > 0; o >>= 1){
        if (threadIdx.x < o) sm[threadIdx.x] += sm[threadIdx.x + o];
        __syncthreads();
    }
    if (threadIdx.x == 0) partial[blockIdx.x] = sm[0];
}

__global__ void k_abs_final(const float* __restrict__ partial, float inv_n, float* __restrict__ out){
    __shared__ float sm[256];
    sm[threadIdx.x] = partial[threadIdx.x]; __syncthreads();
    for (int o = 128; o > 0; o >>= 1){
        if (threadIdx.x < o) sm[threadIdx.x] += sm[threadIdx.x + o];
        __syncthreads();
    }
    if (threadIdx.x == 0) *out = sm[0] * inv_n + 1e-8f;
}

__global__ void k_quant_t(const float* __restrict__ W, bf16* __restrict__ T, int n,
                          const float* __restrict__ sp){
    float s = *sp;
    for (int i = blockIdx.x * 256 + threadIdx.x; i < n; i += gridDim.x * 256){
        float t = rintf(W[i] / s);
        t = fminf(fmaxf(t, -1.0f), 1.0f);
        T[i] = __float2bfloat16_rn(t);
    }
}

// ---------------- bitshift norm -> hi/lo bf16 ---------------------------------
__global__ void k_norm(const float* __restrict__ x, const float* __restrict__ gamma,
                       const float* __restrict__ step, bf16* __restrict__ xh,
                       bf16* __restrict__ xl){
    __shared__ float sm[256];
    __shared__ float s_mean, s_g;
    int row = blockIdx.x;
    const float4* xr = (const float4*)(x + (size_t)row * DM);
    float4 v = xr[threadIdx.x];
    sm[threadIdx.x] = v.x + v.y + v.z + v.w; __syncthreads();
    for (int o = 128; o > 0; o >>= 1){
        if (threadIdx.x < o) sm[threadIdx.x] += sm[threadIdx.x + o];
        __syncthreads();
    }
    if (threadIdx.x == 0) s_mean = sm[0] * (1.0f / DM);
    __syncthreads();
    float mean = s_mean;
    float cx = v.x - mean, cy = v.y - mean, cz = v.z - mean, cw = v.w - mean;
    sm[threadIdx.x] = cx*cx + cy*cy + cz*cz + cw*cw; __syncthreads();
    for (int o = 128; o > 0; o >>= 1){
        if (threadIdx.x < o) sm[threadIdx.x] += sm[threadIdx.x + o];
        __syncthreads();
    }
    if (threadIdx.x == 0){
        float var = sm[0] * (1.0f / DM);
        float vv = var + 1e-9f;
        float sc = 1.0f;
        if (vv >= 4.0f)     sc = 0.5f;
        if (vv >= 16.0f)    sc = 0.25f;
        if (vv >= 64.0f)    sc = 0.125f;
        if (vv >= 256.0f)   sc = 0.0625f;
        if (vv >= 1024.0f)  sc = 0.03125f;
        if (vv >= 4096.0f)  sc = 0.015625f;
        if (vv >= 16384.0f) sc = 0.0078125f;
        if (vv >= 65536.0f) sc = 0.00390625f;
        if (vv < 1.0f)      sc = 1.0f;
        if (vv < 0.25f)     sc = 2.0f;
        if (vv < 0.0625f)   sc = 4.0f;
        s_g = sc * step[0];
    }
    __syncthreads();
    float g = s_g;
    float4 gm = ((const float4*)gamma)[threadIdx.x];
    float o0 = cx*g*gm.x, o1 = cy*g*gm.y, o2 = cz*g*gm.z, o3 = cw*g*gm.w;
    size_t base = (size_t)row * DM + threadIdx.x * 4;
    bf16 h, l;
    split_bf(o0, h, l); xh[base+0]=h; xl[base+0]=l;
    split_bf(o1, h, l); xh[base+1]=h; xl[base+1]=l;
    split_bf(o2, h, l); xh[base+2]=h; xl[base+2]=l;
    split_bf(o3, h, l); xh[base+3]=h; xl[base+3]=l;
}

// ---------------- tensor-core GEMM: C = s * (A @ Bw^T) ------------------------
// A split as Ah+Al (bf16 [M][K]); Bw ternary bf16 [N][K]; fp32 accumulate.
// EPI: 0 fp32 C0 | 1 decay(+bias)->C0 | 2 +resid->C0 | 3 hi/lo bf16 -> H0,H1
//      4 split: n<DI -> C0 (raw), n>=DI -> C1 = squareplus(v)
#define RS 24                    /* padded smem row stride in bf16 elems */

__device__ __forceinline__ void cp16(uint32_t saddr, const bf16* gptr){
    asm volatile("cp.async.cg.shared.global [%0],[%1],16;\n" :: "r"(saddr), "l"(gptr));
}
__device__ __forceinline__ void ldsm4(uint32_t* r, uint32_t a){
    asm volatile("ldmatrix.sync.aligned.m8n8.x4.shared.b16 {%0,%1,%2,%3},[%4];\n"
        : "=r"(r[0]), "=r"(r[1]), "=r"(r[2]), "=r"(r[3]) : "r"(a));
}
__device__ __forceinline__ void mma16816(float* c, const uint32_t* a, uint32_t b0, uint32_t b1){
    asm volatile(
        "mma.sync.aligned.m16n8k16.row.col.f32.bf16.bf16.f32 "
        "{%0,%1,%2,%3},{%4,%5,%6,%7},{%8,%9},{%0,%1,%2,%3};\n"
        : "+f"(c[0]), "+f"(c[1]), "+f"(c[2]), "+f"(c[3])
        : "r"(a[0]), "r"(a[1]), "r"(a[2]), "r"(a[3]), "r"(b0), "r"(b1));
}

// Stage load: BM=128, 256 threads. Each thread issues one 16B cp.async per operand.
template<int BN>
__device__ __forceinline__ void ld_stage(uint32_t sbase, const bf16* __restrict__ Ah,
                                         const bf16* __restrict__ Al,
                                         const bf16* __restrict__ Bw,
                                         int m0, int n0, int K, int kb, int tid){
    const int A_SZ = 128 * RS;
    int r  = tid >> 1;
    int sg = (tid & 1) * 8;
    cp16(sbase + (uint32_t)(r*RS + sg)*2,          Ah + (size_t)(m0 + r)*K + kb + sg);
    cp16(sbase + (uint32_t)(A_SZ + r*RS + sg)*2,   Al + (size_t)(m0 + r)*K + kb + sg);
    if (tid < BN*2)
        cp16(sbase + (uint32_t)(2*A_SZ + r*RS + sg)*2, Bw + (size_t)(n0 + r)*K + kb + sg);
    asm volatile("cp.async.commit_group;\n" ::);
}

template<int BN, int EPI>
__global__ __launch_bounds__(256)
void k_gemm_bf(const bf16* __restrict__ Ah, const bf16* __restrict__ Al,
               const bf16* __restrict__ Bw, int M, int N, int K,
               const float* __restrict__ scale_p,
               const float* __restrict__ bias,
               const float* __restrict__ resid,
               float* __restrict__ C0, float* __restrict__ C1,
               bf16* __restrict__ H0, bf16* __restrict__ H1){
    const int A_SZ = 128 * RS;
    const int STG  = 2*A_SZ + BN*RS;
    const int NT   = BN / 16;            // 8-col n-tiles per warp (per 16-wide group: 2)
    const int NG   = BN / 32;            // 16-n groups per warp
    __shared__ __align__(128) bf16 smem[2][2*128*RS + BN*RS];

    const int tid = threadIdx.x;
    const int m0 = blockIdx.y * 128, n0 = blockIdx.x * BN;
    const int lane = tid & 31, w = tid >> 5;
    const int wm = w >> 1, wn = w & 1;
    const int m0w = wm * 32, n0w = wn * (BN/2);

    float acc[2][8][4];
#pragma unroll
    for (int i = 0; i < 2; i++)
#pragma unroll
        for (int j = 0; j < 8; j++)
#pragma unroll
            for (int q = 0; q < 4; q++) acc[i][j][q] = 0.0f;

    const int aoff = (m0w + (lane & 15)) * RS + (lane >> 4) * 8;
    const int boff = (n0w + ((lane >> 4) << 3) + (lane & 7)) * RS + ((lane >> 3) & 1) * 8;
    const int NITER = K / 16;

    uint32_t sb0 = (uint32_t)__cvta_generic_to_shared(&smem[0][0]);
    uint32_t sb1 = (uint32_t)__cvta_generic_to_shared(&smem[1][0]);

    ld_stage<BN>(sb0, Ah, Al, Bw, m0, n0, K, 0, tid);

    for (int it = 0; it < NITER; it++){
        if (it + 1 < NITER){
            ld_stage<BN>((it & 1) ? sb0 : sb1, Ah, Al, Bw, m0, n0, K, (it + 1) * 16, tid);
            asm volatile("cp.async.wait_group 1;\n" ::);
        } else {
            asm volatile("cp.async.wait_group 0;\n" ::);
        }
        __syncthreads();

        uint32_t sbase = (it & 1) ? sb1 : sb0;
        uint32_t ah0[4], ah1[4], al0[4], al1[4], bq[4][4];
        ldsm4(ah0, sbase + (uint32_t)(aoff)*2);
        ldsm4(ah1, sbase + (uint32_t)(aoff + 16*RS)*2);
        ldsm4(al0, sbase + (uint32_t)(A_SZ + aoff)*2);
        ldsm4(al1, sbase + (uint32_t)(A_SZ + aoff + 16*RS)*2);
#pragma unroll
        for (int j = 0; j < NG; j++)
            ldsm4(bq[j], sbase + (uint32_t)(2*A_SZ + boff + j*16*RS)*2);

#pragma unroll
        for (int j = 0; j < NG; j++){
            mma16816(acc[0][2*j],   ah0, bq[j][0], bq[j][1]);
            mma16816(acc[0][2*j],   al0, bq[j][0], bq[j][1]);
            mma16816(acc[0][2*j+1], ah0, bq[j][2], bq[j][3]);
            mma16816(acc[0][2*j+1], al0, bq[j][2], bq[j][3]);
            mma16816(acc[1][2*j],   ah1, bq[j][0], bq[j][1]);
            mma16816(acc[1][2*j],   al1, bq[j][0], bq[j][1]);
            mma16816(acc[1][2*j+1], ah1, bq[j][2], bq[j][3]);
            mma16816(acc[1][2*j+1], al1, bq[j][2], bq[j][3]);
        }
        __syncthreads();
    }

    float s = *scale_p;
#pragma unroll
    for (int mt = 0; mt < 2; mt++){
        int r0 = m0 + m0w + mt*16 + (lane >> 2);
        int r1 = r0 + 8;
#pragma unroll
        for (int nt = 0; nt < NT; nt++){
            int c = n0 + n0w + nt*8 + (lane & 3)*2;
            float v0 = acc[mt][nt][0]*s, v1 = acc[mt][nt][1]*s;
            float v2 = acc[mt][nt][2]*s, v3 = acc[mt][nt][3]*s;
            if (EPI == 0){
                C0[(size_t)r0*N + c] = v0; C0[(size_t)r0*N + c+1] = v1;
                C0[(size_t)r1*N + c] = v2; C0[(size_t)r1*N + c+1] = v3;
            } else if (EPI == 1){
                C0[(size_t)r0*N + c]   = decay_f(v0 + bias[c]);
                C0[(size_t)r0*N + c+1] = decay_f(v1 + bias[c+1]);
                C0[(size_t)r1*N + c]   = decay_f(v2 + bias[c]);
                C0[(size_t)r1*N + c+1] = decay_f(v3 + bias[c+1]);
            } else if (EPI == 2){
                C0[(size_t)r0*N + c]   = v0 + resid[(size_t)r0*N + c];
                C0[(size_t)r0*N + c+1] = v1 + resid[(size_t)r0*N + c+1];
                C0[(size_t)r1*N + c]   = v2 + resid[(size_t)r1*N + c];
                C0[(size_t)r1*N + c+1] = v3 + resid[(size_t)r1*N + c+1];
            } else if (EPI == 3){
                bf16 h, l;
                split_bf(v0, h, l); H0[(size_t)r0*N + c]   = h; H1[(size_t)r0*N + c]   = l;
                split_bf(v1, h, l); H0[(size_t)r0*N + c+1] = h; H1[(size_t)r0*N + c+1] = l;
                split_bf(v2, h, l); H0[(size_t)r1*N + c]   = h; H1[(size_t)r1*N + c]   = l;
                split_bf(v3, h, l); H0[(size_t)r1*N + c+1] = h; H1[(size_t)r1*N + c+1] = l;
            } else {  // EPI == 4
                float vv0[2] = {v0, v1}, vv1[2] = {v2, v3};
#pragma unroll
                for (int q = 0; q < 2; q++){
                    int cc = c + q;
                    if (cc < DI){
                        C0[(size_t)r0*DI + cc] = vv0[q];
                        C0[(size_t)r1*DI + cc] = vv1[q];
                    } else {
                        C1[(size_t)r0*DI + cc - DI] = squareplus_f(vv0[q]);
                        C1[(size_t)r1*DI + cc - DI] = squareplus_f(vv1[q]);
                    }
                }
            }
        }
    }
}

// ---------------- causal depthwise conv1d(k=4) + squareplus -> hi/lo ---------
__global__ void k_conv(const float* __restrict__ xcraw, const float* __restrict__ cw,
                       const float* __restrict__ cb, bf16* __restrict__ xh,
                       bf16* __restrict__ xl, int total){
    for (int idx = blockIdx.x * 256 + threadIdx.x; idx < total; idx += gridDim.x * 256){
        int d = idx & (DI - 1);
        int m = idx >> 11;
        int t = m & (LL - 1);
        float w0 = cw[d*4+0], w1 = cw[d*4+1], w2 = cw[d*4+2], w3 = cw[d*4+3];
        float s = cb[d] + w3 * xcraw[idx];
        if (t >= 1) s += w2 * xcraw[idx - DI];
        if (t >= 2) s += w1 * xcraw[idx - 2*DI];
        if (t >= 3) s += w0 * xcraw[idx - 3*DI];
        float v = squareplus_f(s);
        bf16 h, l; split_bf(v, h, l);
        xh[idx] = h; xl[idx] = l;
    }
}

// ---------------- chunked scan + fused y = h * spz -> hi/lo bf16 -------------
__global__ void k_scan(const bf16* __restrict__ uh, const bf16* __restrict__ ul,
                       const float* __restrict__ a, const float* __restrict__ spz,
                       bf16* __restrict__ yh, bf16* __restrict__ yl){
    const int c = blockIdx.x * 32 + threadIdx.x;
    const int b = blockIdx.y;
    const int slice = threadIdx.y;                 // 0..15
    const int CH = LL / 16;                        // 128
    size_t base = ((size_t)b * LL) * DI + c;
    int t0 = slice * CH;

    float A = 1.0f, Bv = 0.0f;
    size_t idx = base + (size_t)t0 * DI;
    for (int t = 0; t < CH; t++, idx += DI){
        float at = a[idx];
        float ut = __bfloat162float(uh[idx]) + __bfloat162float(ul[idx]);
        Bv = at * Bv + (1.0f - at) * ut;
        A *= at;
    }
    __shared__ float sA[16][32], sB[16][32], sP[16][32];
    sA[slice][threadIdx.x] = A;
    sB[slice][threadIdx.x] = Bv;
    __syncthreads();
    if (slice == 0){
        float carry = 0.0f;
#pragma unroll
        for (int s2 = 0; s2 < 16; s2++){
            sP[s2][threadIdx.x] = carry;
            carry = sA[s2][threadIdx.x] * carry + sB[s2][threadIdx.x];
        }
    }
    __syncthreads();
    float h = sP[slice][threadIdx.x];
    idx = base + (size_t)t0 * DI;
    for (int t = 0; t < CH; t++, idx += DI){
        float at = a[idx];
        float ut = __bfloat162float(uh[idx]) + __bfloat162float(ul[idx]);
        h = at * h + (1.0f - at) * ut;
        float y = h * spz[idx];
        bf16 hh, llv; split_bf(y, hh, llv);
        yh[idx] = hh; yl[idx] = llv;
    }
}

// ---------------- launch ------------------------------------------------------
extern "C" void kernel_launch(void* const* d_in, const int* in_sizes, int n_in,
                              void* d_out, int out_size){
    const float* x     = (const float*)d_in[0];
    const float* gamma = (const float*)d_in[1];
    const float* step  = (const float*)d_in[2];
    const float* W_in  = (const float*)d_in[3];
    const float* cw    = (const float*)d_in[4];
    const float* cb    = (const float*)d_in[5];
    const float* W_x   = (const float*)d_in[6];
    const float* W_dt  = (const float*)d_in[7];
    const float* b_dt  = (const float*)d_in[8];
    const float* W_out = (const float*)d_in[9];
    float* out = (float*)d_out;

    bf16 *p_xnh, *p_xnl, *p_xch, *p_xcl, *p_dblh, *p_dbll, *p_yh, *p_yl;
    bf16 *p_tin, *p_tx, *p_tdt, *p_tout;
    float *p_xcraw, *p_spz, *p_decay, *p_scale, *p_part;
    cudaGetSymbolAddress((void**)&p_xnh,   g_xn_h);
    cudaGetSymbolAddress((void**)&p_xnl,   g_xn_l);
    cudaGetSymbolAddress((void**)&p_xcraw, g_xcraw);
    cudaGetSymbolAddress((void**)&p_spz,   g_spz);
    cudaGetSymbolAddress((void**)&p_xch,   g_xc_h);
    cudaGetSymbolAddress((void**)&p_xcl,   g_xc_l);
    cudaGetSymbolAddress((void**)&p_dblh,  g_dbl_h);
    cudaGetSymbolAddress((void**)&p_dbll,  g_dbl_l);
    cudaGetSymbolAddress((void**)&p_decay, g_decay);
    cudaGetSymbolAddress((void**)&p_yh,    g_y_h);
    cudaGetSymbolAddress((void**)&p_yl,    g_y_l);
    cudaGetSymbolAddress((void**)&p_tin,   g_t_in);
    cudaGetSymbolAddress((void**)&p_tx,    g_t_x);
    cudaGetSymbolAddress((void**)&p_tdt,   g_t_dt);
    cudaGetSymbolAddress((void**)&p_tout,  g_t_out);
    cudaGetSymbolAddress((void**)&p_scale, g_scale);
    cudaGetSymbolAddress((void**)&p_part,  g_part);

    // 1) ternary scales + exact-ternary bf16 weights
    k_abs_partial<<<256,256>>>(W_in,  4096*1024, p_part + 0*256);
    k_abs_final  <<<1,256>>>(p_part + 0*256, 1.0f/4194304.0f, p_scale + 0);
    k_abs_partial<<<256,256>>>(W_x,   96*2048,  p_part + 1*256);
    k_abs_final  <<<1,256>>>(p_part + 1*256, 1.0f/196608.0f,  p_scale + 1);
    k_abs_partial<<<256,256>>>(W_dt,  2048*64,  p_part + 2*256);
    k_abs_final  <<<1,256>>>(p_part + 2*256, 1.0f/131072.0f,  p_scale + 2);
    k_abs_partial<<<256,256>>>(W_out, 1024*2048,p_part + 3*256);
    k_abs_final  <<<1,256>>>(p_part + 3*256, 1.0f/2097152.0f, p_scale + 3);

    k_quant_t<<<2048,256>>>(W_in,  p_tin,  4194304, p_scale + 0);
    k_quant_t<<<256, 256>>>(W_x,   p_tx,   131072,  p_scale + 1);  // first 64 rows
    k_quant_t<<<256, 256>>>(W_dt,  p_tdt,  131072,  p_scale + 2);
    k_quant_t<<<1024,256>>>(W_out, p_tout, 2097152, p_scale + 3);

    // 2) norm -> hi/lo bf16
    k_norm<<<M_TOK,256>>>(x, gamma, step, p_xnh, p_xnl);

    // 3) in-projection (tensor cores), epilogue splits xc_raw | squareplus(z)
    k_gemm_bf<128,4><<<dim3(32,64),256>>>(p_xnh, p_xnl, p_tin, M_TOK, 4096, 1024,
                                          p_scale+0, nullptr, nullptr,
                                          p_xcraw, p_spz, nullptr, nullptr);

    // 4) causal conv + squareplus -> xc hi/lo
    k_conv<<<65536,256>>>(p_xcraw, cw, cb, p_xch, p_xcl, M_TOK * DI);

    // 5) dt_rank projection -> dbl hi/lo
    k_gemm_bf<64,3><<<dim3(1,64),256>>>(p_xch, p_xcl, p_tx, M_TOK, 64, 2048,
                                        p_scale+1, nullptr, nullptr,
                                        nullptr, nullptr, p_dblh, p_dbll);

    // 6) dt projection + fused sigmoid + dyadic round -> decay
    k_gemm_bf<128,1><<<dim3(16,64),256>>>(p_dblh, p_dbll, p_tdt, M_TOK, 2048, 64,
                                          p_scale+2, b_dt, nullptr,
                                          p_decay, nullptr, nullptr, nullptr);

    // 7) scan + fused y = h * spz -> hi/lo
    k_scan<<<dim3(DI/32, BB), dim3(32,16)>>>(p_xch, p_xcl, p_decay, p_spz, p_yh, p_yl);

    // 8) out-projection + residual -> d_out
    k_gemm_bf<128,2><<<dim3(8,64),256>>>(p_yh, p_yl, p_tout, M_TOK, 1024, 2048,
                                         p_scale+3, nullptr, x,
                                         out, nullptr, nullptr, nullptr);
}

// round 4
// speedup vs baseline: 3.6723x; 1.2453x over previous
#include <cuda_runtime.h>
#include <cuda_bf16.h>
#include <math.h>
#include <stdint.h>

#define BB 4
#define LL 2048
#define DM 1024
#define DI 2048
#define DTR 64
#define M_TOK (BB*LL)           // 8192

typedef __nv_bfloat16 bf16;

// ---------------- scratch (device globals; allocation is forbidden) ----------
__device__ __align__(256) bf16  g_xn_h [M_TOK * DM];
__device__ __align__(256) bf16  g_xn_l [M_TOK * DM];
__device__ __align__(256) float g_xcraw[M_TOK * DI];
__device__ __align__(256) float g_spz  [M_TOK * DI];
__device__ __align__(256) bf16  g_xc_h [M_TOK * DI];
__device__ __align__(256) bf16  g_xc_l [M_TOK * DI];
__device__ __align__(256) bf16  g_dbl_h[M_TOK * DTR];
__device__ __align__(256) bf16  g_dbl_l[M_TOK * DTR];
__device__ __align__(256) unsigned short g_decay16[M_TOK * DI];
__device__ __align__(256) bf16  g_y_h  [M_TOK * DI];
__device__ __align__(256) bf16  g_y_l  [M_TOK * DI];
__device__ __align__(256) bf16  g_t_in [4096*1024];
__device__ __align__(256) bf16  g_t_x  [64*2048];
__device__ __align__(256) bf16  g_t_dt [2048*64];
__device__ __align__(256) bf16  g_t_out[1024*2048];
__device__ __align__(256) float g_scale[4];
__device__ __align__(256) float g_part [4*256];

// ---------------- exact reference math ---------------------------------------
__device__ __forceinline__ float squareplus_f(float x){
    float y = fminf(fmaxf(x*x + 4.0f, 1e-6f), 1e6f);
    float r = (y > 16.0f) ? 0.125f : 0.5f;
    if (y > 64.0f)  r = 0.0625f;
    if (y > 256.0f) r = 0.03125f;
    if (y < 4.0f)   r = 1.0f;
    if (y < 1.0f)   r = 2.0f;
    if (y < 0.25f)  r = 4.0f;
#pragma unroll
    for (int i = 0; i < 3; i++){
        r = r * (1.5f - 0.5f * y * r * r);
        r = fminf(fmaxf(r, 1e-6f), 1e3f);
    }
    float s = fminf(fmaxf(y * r, 0.0f), 1e3f);
    return 0.5f * (x + s);
}

__device__ __forceinline__ unsigned short decay_u16(float z){
    float sg = 0.5f + 0.5f * z / (1.0f + fabsf(z));
    return (unsigned short)(int)rintf(sg * 32768.0f);
}

__device__ __forceinline__ void split_bf(float v, bf16& h, bf16& l){
    h = __float2bfloat16_rn(v);
    l = __float2bfloat16_rn(v - __bfloat162float(h));
}

// ---------------- weight scale: deterministic 2-level reduction --------------
__global__ void k_abs_partial(const float* __restrict__ W, int n4, float* __restrict__ partial){
    __shared__ float sm[256];
    float s = 0.0f;
    for (int i = blockIdx.x * 256 + threadIdx.x; i < n4; i += gridDim.x * 256){
        float4 v = ((const float4*)W)[i];
        s += fabsf(v.x) + fabsf(v.y) + fabsf(v.z) + fabsf(v.w);
    }
    sm[threadIdx.x] = s; __syncthreads();
    for (int o = 128; o > 0; o >>= 1){
        if (threadIdx.x < o) sm[threadIdx.x] += sm[threadIdx.x + o];
        __syncthreads();
    }
    if (threadIdx.x == 0) partial[blockIdx.x] = sm[0];
}

__global__ void k_abs_final(const float* __restrict__ partial, float inv_n, float* __restrict__ out){
    __shared__ float sm[256];
    sm[threadIdx.x] = partial[threadIdx.x]; __syncthreads();
    for (int o = 128; o > 0; o >>= 1){
        if (threadIdx.x < o) sm[threadIdx.x] += sm[threadIdx.x + o];
        __syncthreads();
    }
    if (threadIdx.x == 0) *out = sm[0] * inv_n + 1e-8f;
}

__global__ void k_quant_t(const float* __restrict__ W, bf16* __restrict__ T, int n4,
                          const float* __restrict__ sp){
    float s = *sp;
    for (int i = blockIdx.x * 256 + threadIdx.x; i < n4; i += gridDim.x * 256){
        float4 v = ((const float4*)W)[i];
        float t0 = fminf(fmaxf(rintf(v.x / s), -1.0f), 1.0f);
        float t1 = fminf(fmaxf(rintf(v.y / s), -1.0f), 1.0f);
        float t2 = fminf(fmaxf(rintf(v.z / s), -1.0f), 1.0f);
        float t3 = fminf(fmaxf(rintf(v.w / s), -1.0f), 1.0f);
        __nv_bfloat162 p0 = __floats2bfloat162_rn(t0, t1);
        __nv_bfloat162 p1 = __floats2bfloat162_rn(t2, t3);
        uint2 u; u.x = *(uint32_t*)&p0; u.y = *(uint32_t*)&p1;
        ((uint2*)T)[i] = u;
    }
}

// ---------------- bitshift norm -> hi/lo bf16 ---------------------------------
__global__ void k_norm(const float* __restrict__ x, const float* __restrict__ gamma,
                       const float* __restrict__ step, bf16* __restrict__ xh,
                       bf16* __restrict__ xl){
    __shared__ float sm[256];
    __shared__ float s_mean, s_g;
    int row = blockIdx.x;
    const float4* xr = (const float4*)(x + (size_t)row * DM);
    float4 v = xr[threadIdx.x];
    sm[threadIdx.x] = v.x + v.y + v.z + v.w; __syncthreads();
    for (int o = 128; o > 0; o >>= 1){
        if (threadIdx.x < o) sm[threadIdx.x] += sm[threadIdx.x + o];
        __syncthreads();
    }
    if (threadIdx.x == 0) s_mean = sm[0] * (1.0f / DM);
    __syncthreads();
    float mean = s_mean;
    float cx = v.x - mean, cy = v.y - mean, cz = v.z - mean, cw = v.w - mean;
    sm[threadIdx.x] = cx*cx + cy*cy + cz*cz + cw*cw; __syncthreads();
    for (int o = 128; o > 0; o >>= 1){
        if (threadIdx.x < o) sm[threadIdx.x] += sm[threadIdx.x + o];
        __syncthreads();
    }
    if (threadIdx.x == 0){
        float var = sm[0] * (1.0f / DM);
        float vv = var + 1e-9f;
        float sc = 1.0f;
        if (vv >= 4.0f)     sc = 0.5f;
        if (vv >= 16.0f)    sc = 0.25f;
        if (vv >= 64.0f)    sc = 0.125f;
        if (vv >= 256.0f)   sc = 0.0625f;
        if (vv >= 1024.0f)  sc = 0.03125f;
        if (vv >= 4096.0f)  sc = 0.015625f;
        if (vv >= 16384.0f) sc = 0.0078125f;
        if (vv >= 65536.0f) sc = 0.00390625f;
        if (vv < 1.0f)      sc = 1.0f;
        if (vv < 0.25f)     sc = 2.0f;
        if (vv < 0.0625f)   sc = 4.0f;
        s_g = sc * step[0];
    }
    __syncthreads();
    float g = s_g;
    float4 gm = ((const float4*)gamma)[threadIdx.x];
    float o0 = cx*g*gm.x, o1 = cy*g*gm.y, o2 = cz*g*gm.z, o3 = cw*g*gm.w;
    size_t base = (size_t)row * DM + threadIdx.x * 4;
    bf16 h, l;
    split_bf(o0, h, l); xh[base+0]=h; xl[base+0]=l;
    split_bf(o1, h, l); xh[base+1]=h; xl[base+1]=l;
    split_bf(o2, h, l); xh[base+2]=h; xl[base+2]=l;
    split_bf(o3, h, l); xh[base+3]=h; xl[base+3]=l;
}

// ---------------- tensor-core GEMM: C = s * (A @ Bw^T) ------------------------
// BK=32, 3-stage cp.async pipeline, 1 syncthreads/iter.
// EPI: 1 decay->u16 | 2 +resid->C0 | 3 hi/lo bf16 -> H0,H1 | 4 split xcraw|spz
#define RSG 40                    /* padded smem row stride (bf16 elems), 80B */

__device__ __forceinline__ void cp16(uint32_t saddr, const bf16* gptr){
    asm volatile("cp.async.cg.shared.global [%0],[%1],16;\n" :: "r"(saddr), "l"(gptr));
}
__device__ __forceinline__ void ldsm4(uint32_t* r, uint32_t a){
    asm volatile("ldmatrix.sync.aligned.m8n8.x4.shared.b16 {%0,%1,%2,%3},[%4];\n"
        : "=r"(r[0]), "=r"(r[1]), "=r"(r[2]), "=r"(r[3]) : "r"(a));
}
__device__ __forceinline__ void mma16816(float* c, const uint32_t* a, uint32_t b0, uint32_t b1){
    asm volatile(
        "mma.sync.aligned.m16n8k16.row.col.f32.bf16.bf16.f32 "
        "{%0,%1,%2,%3},{%4,%5,%6,%7},{%8,%9},{%0,%1,%2,%3};\n"
        : "+f"(c[0]), "+f"(c[1]), "+f"(c[2]), "+f"(c[3])
        : "r"(a[0]), "r"(a[1]), "r"(a[2]), "r"(a[3]), "r"(b0), "r"(b1));
}

template<int BN>
__device__ __forceinline__ void ld_stage(uint32_t sbase, const bf16* __restrict__ Ah,
                                         const bf16* __restrict__ Al,
                                         const bf16* __restrict__ Bw,
                                         int m0, int n0, int K, int kb, int tid){
    constexpr int A_SZ = 128 * RSG;
#pragma unroll
    for (int j = 0; j < 2; j++){
        int idx = tid + j*256;
        int r = idx >> 2, sg = (idx & 3) * 8;
        cp16(sbase + (uint32_t)(r*RSG + sg)*2, Ah + (size_t)(m0 + r)*K + kb + sg);
    }
#pragma unroll
    for (int j = 0; j < 2; j++){
        int idx = tid + j*256;
        int r = idx >> 2, sg = (idx & 3) * 8;
        cp16(sbase + (uint32_t)(A_SZ + r*RSG + sg)*2, Al + (size_t)(m0 + r)*K + kb + sg);
    }
#pragma unroll
    for (int j = 0; j < BN*4/256; j++){
        int idx = tid + j*256;
        int r = idx >> 2, sg = (idx & 3) * 8;
        cp16(sbase + (uint32_t)(2*A_SZ + r*RSG + sg)*2, Bw + (size_t)(n0 + r)*K + kb + sg);
    }
    asm volatile("cp.async.commit_group;\n" ::);
}

template<int BN, int EPI>
__global__ __launch_bounds__(256, 2)
void k_gemm_bf(const bf16* __restrict__ Ah, const bf16* __restrict__ Al,
               const bf16* __restrict__ Bw, int M, int N, int K,
               const float* __restrict__ scale_p,
               const float* __restrict__ bias,
               const float* __restrict__ resid,
               float* __restrict__ C0, float* __restrict__ C1,
               bf16* __restrict__ H0, bf16* __restrict__ H1,
               unsigned short* __restrict__ U16){
    constexpr int A_SZ = 128 * RSG;
    constexpr int B_SZ = BN * RSG;
    constexpr int STG  = 2*A_SZ + B_SZ;
    constexpr int NG = BN / 32;
    constexpr int NT = BN / 16;
    extern __shared__ __align__(16) bf16 smem[];

    const int tid = threadIdx.x;
    const int m0 = blockIdx.y * 128, n0 = blockIdx.x * BN;
    const int lane = tid & 31, w = tid >> 5;
    const int wm = w >> 1, wn = w & 1;
    const int m0w = wm * 32, n0w = wn * (BN/2);

    float acc[2][NT][4];
#pragma unroll
    for (int i = 0; i < 2; i++)
#pragma unroll
        for (int j = 0; j < NT; j++)
#pragma unroll
            for (int q = 0; q < 4; q++) acc[i][j][q] = 0.0f;

    const int aoff = (m0w + (lane & 15)) * RSG + (lane >> 4) * 8;
    const int boff = (n0w + ((lane >> 4) << 3) + (lane & 7)) * RSG + ((lane >> 3) & 1) * 8;
    const int NITER = K / 32;
    uint32_t sb = (uint32_t)__cvta_generic_to_shared(smem);

    ld_stage<BN>(sb,           Ah, Al, Bw, m0, n0, K, 0,  tid);
    ld_stage<BN>(sb + STG*2,   Ah, Al, Bw, m0, n0, K, 32, tid);

    for (int it = 0; it < NITER; it++){
        if (it + 1 < NITER) asm volatile("cp.async.wait_group 1;\n" ::);
        else                asm volatile("cp.async.wait_group 0;\n" ::);
        __syncthreads();
        if (it + 2 < NITER)
            ld_stage<BN>(sb + (uint32_t)(((it+2)%3)*STG)*2, Ah, Al, Bw, m0, n0, K, (it+2)*32, tid);

        uint32_t sbase = sb + (uint32_t)((it%3)*STG)*2;
#pragma unroll
        for (int ks = 0; ks < 2; ks++){
            int ko = ks * 16;
            uint32_t ah0[4], ah1[4], al0[4], al1[4], bq[NG][4];
            ldsm4(ah0, sbase + (uint32_t)(aoff + ko)*2);
            ldsm4(ah1, sbase + (uint32_t)(aoff + 16*RSG + ko)*2);
            ldsm4(al0, sbase + (uint32_t)(A_SZ + aoff + ko)*2);
            ldsm4(al1, sbase + (uint32_t)(A_SZ + aoff + 16*RSG + ko)*2);
#pragma unroll
            for (int j = 0; j < NG; j++)
                ldsm4(bq[j], sbase + (uint32_t)(2*A_SZ + boff + j*16*RSG + ko)*2);
#pragma unroll
            for (int j = 0; j < NG; j++){
                mma16816(acc[0][2*j],   ah0, bq[j][0], bq[j][1]);
                mma16816(acc[0][2*j],   al0, bq[j][0], bq[j][1]);
                mma16816(acc[0][2*j+1], ah0, bq[j][2], bq[j][3]);
                mma16816(acc[0][2*j+1], al0, bq[j][2], bq[j][3]);
                mma16816(acc[1][2*j],   ah1, bq[j][0], bq[j][1]);
                mma16816(acc[1][2*j],   al1, bq[j][0], bq[j][1]);
                mma16816(acc[1][2*j+1], ah1, bq[j][2], bq[j][3]);
                mma16816(acc[1][2*j+1], al1, bq[j][2], bq[j][3]);
            }
        }
    }

    float s = *scale_p;
#pragma unroll
    for (int mt = 0; mt < 2; mt++){
        int r0 = m0 + m0w + mt*16 + (lane >> 2);
        int r1 = r0 + 8;
#pragma unroll
        for (int nt = 0; nt < NT; nt++){
            int c = n0 + n0w + nt*8 + (lane & 3)*2;
            float v0 = acc[mt][nt][0]*s, v1 = acc[mt][nt][1]*s;
            float v2 = acc[mt][nt][2]*s, v3 = acc[mt][nt][3]*s;
            if (EPI == 1){
                U16[(size_t)r0*N + c]   = decay_u16(v0 + bias[c]);
                U16[(size_t)r0*N + c+1] = decay_u16(v1 + bias[c+1]);
                U16[(size_t)r1*N + c]   = decay_u16(v2 + bias[c]);
                U16[(size_t)r1*N + c+1] = decay_u16(v3 + bias[c+1]);
            } else if (EPI == 2){
                C0[(size_t)r0*N + c]   = v0 + resid[(size_t)r0*N + c];
                C0[(size_t)r0*N + c+1] = v1 + resid[(size_t)r0*N + c+1];
                C0[(size_t)r1*N + c]   = v2 + resid[(size_t)r1*N + c];
                C0[(size_t)r1*N + c+1] = v3 + resid[(size_t)r1*N + c+1];
            } else if (EPI == 3){
                bf16 h, l;
                split_bf(v0, h, l); H0[(size_t)r0*N + c]   = h; H1[(size_t)r0*N + c]   = l;
                split_bf(v1, h, l); H0[(size_t)r0*N + c+1] = h; H1[(size_t)r0*N + c+1] = l;
                split_bf(v2, h, l); H0[(size_t)r1*N + c]   = h; H1[(size_t)r1*N + c]   = l;
                split_bf(v3, h, l); H0[(size_t)r1*N + c+1] = h; H1[(size_t)r1*N + c+1] = l;
            } else {  // EPI == 4
                float vv0[2] = {v0, v1}, vv1[2] = {v2, v3};
#pragma unroll
                for (int q = 0; q < 2; q++){
                    int cc = c + q;
                    if (cc < DI){
                        C0[(size_t)r0*DI + cc] = vv0[q];
                        C0[(size_t)r1*DI + cc] = vv1[q];
                    } else {
                        C1[(size_t)r0*DI + cc - DI] = squareplus_f(vv0[q]);
                        C1[(size_t)r1*DI + cc - DI] = squareplus_f(vv1[q]);
                    }
                }
            }
        }
    }
}

// ---------------- causal depthwise conv1d(k=4) + squareplus (x4 vector) ------
__global__ void k_conv(const float* __restrict__ xcraw, const float* __restrict__ cw,
                       const float* __restrict__ cb, bf16* __restrict__ xh,
                       bf16* __restrict__ xl){
    int i = blockIdx.x * 256 + threadIdx.x;       // over total/4 elements
    int idx = i * 4;
    int dv = (idx & (DI - 1)) >> 2;
    int m = idx >> 11;
    int t = m & (LL - 1);
    const float4* x4 = (const float4*)xcraw;
    float4 xt = x4[i];
    float4 z = make_float4(0.f,0.f,0.f,0.f);
    float4 x1 = (t >= 1) ? x4[i - DI/4]   : z;
    float4 x2 = (t >= 2) ? x4[i - 2*DI/4] : z;
    float4 x3 = (t >= 3) ? x4[i - 3*DI/4] : z;
    const float4* cw4 = (const float4*)cw;
    int d0 = dv * 4;
    float4 wa = cw4[d0+0], wb = cw4[d0+1], wc = cw4[d0+2], wd = cw4[d0+3];
    float4 cbv = ((const float4*)cb)[dv];
    float s0 = cbv.x + wa.w*xt.x + wa.z*x1.x + wa.y*x2.x + wa.x*x3.x;
    float s1 = cbv.y + wb.w*xt.y + wb.z*x1.y + wb.y*x2.y + wb.x*x3.y;
    float s2 = cbv.z + wc.w*xt.z + wc.z*x1.z + wc.y*x2.z + wc.x*x3.z;
    float s3 = cbv.w + wd.w*xt.w + wd.z*x1.w + wd.y*x2.w + wd.x*x3.w;
    float v0 = squareplus_f(s0), v1 = squareplus_f(s1);
    float v2 = squareplus_f(s2), v3 = squareplus_f(s3);
    bf16 h0,l0,h1,l1,h2,l2,h3,l3;
    split_bf(v0,h0,l0); split_bf(v1,h1,l1); split_bf(v2,h2,l2); split_bf(v3,h3,l3);
    __nv_bfloat162 ph0 = __nv_bfloat162(h0,h1), ph1 = __nv_bfloat162(h2,h3);
    __nv_bfloat162 pl0 = __nv_bfloat162(l0,l1), pl1 = __nv_bfloat162(l2,l3);
    uint2 uh; uh.x = *(uint32_t*)&ph0; uh.y = *(uint32_t*)&ph1;
    uint2 ul; ul.x = *(uint32_t*)&pl0; ul.y = *(uint32_t*)&pl1;
    ((uint2*)xh)[i] = uh;
    ((uint2*)xl)[i] = ul;
}

// ---------------- chunked scan (32 slices x 64 steps) + fused y --------------
__global__ void k_scan(const bf16* __restrict__ uh, const bf16* __restrict__ ul,
                       const unsigned short* __restrict__ a16,
                       const float* __restrict__ spz,
                       bf16* __restrict__ yh, bf16* __restrict__ yl){
    const int c = blockIdx.x * 32 + threadIdx.x;
    const int b = blockIdx.y;
    const int slice = threadIdx.y;                 // 0..31
    const int CH = LL / 32;                        // 64
    size_t base = ((size_t)b * LL) * DI + c;
    int t0 = slice * CH;

    float A = 1.0f, Bv = 0.0f;
    size_t idx = base + (size_t)t0 * DI;
    for (int t = 0; t < CH; t++, idx += DI){
        float at = (float)a16[idx] * (1.0f/32768.0f);
        float ut = __bfloat162float(uh[idx]) + __bfloat162float(ul[idx]);
        Bv = at * Bv + (1.0f - at) * ut;
        A *= at;
    }
    __shared__ float sA[32][32], sB[32][32], sP[32][32];
    sA[slice][threadIdx.x] = A;
    sB[slice][threadIdx.x] = Bv;
    __syncthreads();
    if (slice == 0){
        float carry = 0.0f;
#pragma unroll
        for (int s2 = 0; s2 < 32; s2++){
            sP[s2][threadIdx.x] = carry;
            carry = sA[s2][threadIdx.x] * carry + sB[s2][threadIdx.x];
        }
    }
    __syncthreads();
    float h = sP[slice][threadIdx.x];
    idx = base + (size_t)t0 * DI;
    for (int t = 0; t < CH; t++, idx += DI){
        float at = (float)a16[idx] * (1.0f/32768.0f);
        float ut = __bfloat162float(uh[idx]) + __bfloat162float(ul[idx]);
        h = at * h + (1.0f - at) * ut;
        float y = h * spz[idx];
        bf16 hh, llv; split_bf(y, hh, llv);
        yh[idx] = hh; yl[idx] = llv;
    }
}

// ---------------- launch ------------------------------------------------------
extern "C" void kernel_launch(void* const* d_in, const int* in_sizes, int n_in,
                              void* d_out, int out_size){
    const float* x     = (const float*)d_in[0];
    const float* gamma = (const float*)d_in[1];
    const float* step  = (const float*)d_in[2];
    const float* W_in  = (const float*)d_in[3];
    const float* cw    = (const float*)d_in[4];
    const float* cb    = (const float*)d_in[5];
    const float* W_x   = (const float*)d_in[6];
    const float* W_dt  = (const float*)d_in[7];
    const float* b_dt  = (const float*)d_in[8];
    const float* W_out = (const float*)d_in[9];
    float* out = (float*)d_out;

    bf16 *p_xnh, *p_xnl, *p_xch, *p_xcl, *p_dblh, *p_dbll, *p_yh, *p_yl;
    bf16 *p_tin, *p_tx, *p_tdt, *p_tout;
    float *p_xcraw, *p_spz, *p_scale, *p_part;
    unsigned short* p_decay;
    cudaGetSymbolAddress((void**)&p_xnh,   g_xn_h);
    cudaGetSymbolAddress((void**)&p_xnl,   g_xn_l);
    cudaGetSymbolAddress((void**)&p_xcraw, g_xcraw);
    cudaGetSymbolAddress((void**)&p_spz,   g_spz);
    cudaGetSymbolAddress((void**)&p_xch,   g_xc_h);
    cudaGetSymbolAddress((void**)&p_xcl,   g_xc_l);
    cudaGetSymbolAddress((void**)&p_dblh,  g_dbl_h);
    cudaGetSymbolAddress((void**)&p_dbll,  g_dbl_l);
    cudaGetSymbolAddress((void**)&p_decay, g_decay16);
    cudaGetSymbolAddress((void**)&p_yh,    g_y_h);
    cudaGetSymbolAddress((void**)&p_yl,    g_y_l);
    cudaGetSymbolAddress((void**)&p_tin,   g_t_in);
    cudaGetSymbolAddress((void**)&p_tx,    g_t_x);
    cudaGetSymbolAddress((void**)&p_tdt,   g_t_dt);
    cudaGetSymbolAddress((void**)&p_tout,  g_t_out);
    cudaGetSymbolAddress((void**)&p_scale, g_scale);
    cudaGetSymbolAddress((void**)&p_part,  g_part);

    const int SM128 = 3*(2*128*RSG + 128*RSG)*2;   // 92160 B
    const int SM64  = 3*(2*128*RSG +  64*RSG)*2;   // 76800 B
    cudaFuncSetAttribute(k_gemm_bf<128,4>, cudaFuncAttributeMaxDynamicSharedMemorySize, SM128);
    cudaFuncSetAttribute(k_gemm_bf< 64,3>, cudaFuncAttributeMaxDynamicSharedMemorySize, SM64);
    cudaFuncSetAttribute(k_gemm_bf<128,1>, cudaFuncAttributeMaxDynamicSharedMemorySize, SM128);
    cudaFuncSetAttribute(k_gemm_bf<128,2>, cudaFuncAttributeMaxDynamicSharedMemorySize, SM128);

    // 1) ternary scales + exact-ternary bf16 weights
    k_abs_partial<<<256,256>>>(W_in,  4096*1024/4, p_part + 0*256);
    k_abs_final  <<<1,256>>>(p_part + 0*256, 1.0f/4194304.0f, p_scale + 0);
    k_abs_partial<<<256,256>>>(W_x,   96*2048/4,  p_part + 1*256);
    k_abs_final  <<<1,256>>>(p_part + 1*256, 1.0f/196608.0f,  p_scale + 1);
    k_abs_partial<<<256,256>>>(W_dt,  2048*64/4,  p_part + 2*256);
    k_abs_final  <<<1,256>>>(p_part + 2*256, 1.0f/131072.0f,  p_scale + 2);
    k_abs_partial<<<256,256>>>(W_out, 1024*2048/4,p_part + 3*256);
    k_abs_final  <<<1,256>>>(p_part + 3*256, 1.0f/2097152.0f, p_scale + 3);

    k_quant_t<<<1024,256>>>(W_in,  p_tin,  4194304/4, p_scale + 0);
    k_quant_t<<<128, 256>>>(W_x,   p_tx,   131072/4,  p_scale + 1);  // first 64 rows
    k_quant_t<<<128, 256>>>(W_dt,  p_tdt,  131072/4,  p_scale + 2);
    k_quant_t<<<512, 256>>>(W_out, p_tout, 2097152/4, p_scale + 3);

    // 2) norm -> hi/lo bf16
    k_norm<<<M_TOK,256>>>(x, gamma, step, p_xnh, p_xnl);

    // 3) in-projection: epilogue splits xc_raw | squareplus(z)
    k_gemm_bf<128,4><<<dim3(32,64),256,SM128>>>(p_xnh, p_xnl, p_tin, M_TOK, 4096, 1024,
                                                p_scale+0, nullptr, nullptr,
                                                p_xcraw, p_spz, nullptr, nullptr, nullptr);

    // 4) causal conv + squareplus -> xc hi/lo
    k_conv<<<M_TOK*DI/4/256,256>>>(p_xcraw, cw, cb, p_xch, p_xcl);

    // 5) dt_rank projection -> dbl hi/lo
    k_gemm_bf<64,3><<<dim3(1,64),256,SM64>>>(p_xch, p_xcl, p_tx, M_TOK, 64, 2048,
                                             p_scale+1, nullptr, nullptr,
                                             nullptr, nullptr, p_dblh, p_dbll, nullptr);

    // 6) dt projection + fused sigmoid + dyadic round -> decay u16
    k_gemm_bf<128,1><<<dim3(16,64),256,SM128>>>(p_dblh, p_dbll, p_tdt, M_TOK, 2048, 64,
                                                p_scale+2, b_dt, nullptr,
                                                nullptr, nullptr, nullptr, nullptr, p_decay);

    // 7) scan + fused y = h * spz -> hi/lo
    k_scan<<<dim3(DI/32, BB), dim3(32,32)>>>(p_xch, p_xcl, p_decay, p_spz, p_yh, p_yl);

    // 8) out-projection + residual -> d_out
    k_gemm_bf<128,2><<<dim3(8,64),256,SM128>>>(p_yh, p_yl, p_tout, M_TOK, 1024, 2048,
                                               p_scale+3, nullptr, x,
                                               out, nullptr, nullptr, nullptr, nullptr);
}